// round 1
// baseline (speedup 1.0000x reference)
#include <cuda_runtime.h>

typedef unsigned long long ull;

#define MT 4096        // tokens
#define DM 64          // d_model
#define NHH 8          // heads
#define HDD 8          // head dim
#define NLAYER 4
#define DFFN 256
#define LNEPS 1e-5f
#define LOG2E_F 1.4426950408889634f
#define QSCALE 0.35355339059327373f   // 1/sqrt(8)

// ---------------- scratch (device globals; no runtime alloc) ----------------
__device__ float g_xbuf[MT*DM];
__device__ float g_x1[MT*DM];
__device__ float g_tmp[MT*DM];
__device__ float g_big[MT*DFFN];     // qkv (192) or ff hidden (256)
__device__ float g_qh[MT*DM];        // [NH][M][HD], q pre-scaled by QSCALE*LOG2E
__device__ float g_kh[MT*DM];
__device__ float g_vh[MT*DM];
__device__ float g_attn[MT*DM];
__device__ float g_xp[MT*DM];        // pruned x
__device__ float g_hnx[MT];          // 0.5*|x|^2*log2e
__device__ float g_hny[MT];
__device__ float g_acc[3];           // gram sums: xx, yy, xy

// ---------------- f32x2 helpers ----------------
__device__ __forceinline__ ull fma2(ull a, ull b, ull c) {
    ull d; asm("fma.rn.f32x2 %0, %1, %2, %3;" : "=l"(d) : "l"(a), "l"(b), "l"(c)); return d;
}
__device__ __forceinline__ ull pack2(float a, float b) {
    ull r; asm("mov.b64 %0, {%1, %2};" : "=l"(r) : "f"(a), "f"(b)); return r;
}
__device__ __forceinline__ void unpack2(ull v, float& a, float& b) {
    asm("mov.b64 {%0, %1}, %2;" : "=f"(a), "=f"(b) : "l"(v));
}
__device__ __forceinline__ float ex2f(float x) {
    float r; asm("ex2.approx.f32 %0, %1;" : "=f"(r) : "f"(x)); return r;
}

// ---------------- generic tiled GEMM: C[M,N] = A[M,K] @ W[N,K]^T + bias (+resid)(+relu) ----
// grid (M/64, N/64), block 256. K in {64,256}, multiples of 64. N multiple of 64.
__global__ void gemm_kernel(const float* __restrict__ A, const float* __restrict__ W,
                            const float* __restrict__ bias, const float* __restrict__ resid,
                            float* __restrict__ C, int N, int K, int relu)
{
    __shared__ float As[64][68];
    __shared__ float Ws[64][68];
    const int tid = threadIdx.x;
    const int r0 = blockIdx.x * 64, n0 = blockIdx.y * 64;
    const int tx = tid & 15, ty = tid >> 4;

    ull acc[4][4];
#pragma unroll
    for (int i = 0; i < 4; i++)
#pragma unroll
        for (int j = 0; j < 4; j++) acc[i][j] = 0ULL;

    for (int kc = 0; kc < K; kc += 64) {
        __syncthreads();
        for (int t = tid; t < 1024; t += 256) {
            int rr = t >> 4, kq = (t & 15) << 2;
            *(float4*)&As[rr][kq] = *(const float4*)&A[(size_t)(r0 + rr) * K + kc + kq];
            *(float4*)&Ws[rr][kq] = *(const float4*)&W[(size_t)(n0 + rr) * K + kc + kq];
        }
        __syncthreads();
#pragma unroll 8
        for (int kk = 0; kk < 32; kk++) {
            ull a[4], w[4];
#pragma unroll
            for (int i = 0; i < 4; i++) a[i] = *(const ull*)&As[ty * 4 + i][kk * 2];
#pragma unroll
            for (int j = 0; j < 4; j++) w[j] = *(const ull*)&Ws[tx * 4 + j][kk * 2];
#pragma unroll
            for (int i = 0; i < 4; i++)
#pragma unroll
                for (int j = 0; j < 4; j++) acc[i][j] = fma2(a[i], w[j], acc[i][j]);
        }
    }

#pragma unroll
    for (int i = 0; i < 4; i++) {
        int r = r0 + ty * 4 + i;
        float o[4];
#pragma unroll
        for (int j = 0; j < 4; j++) {
            int n = n0 + tx * 4 + j;
            float lo, hi; unpack2(acc[i][j], lo, hi);
            float c = lo + hi + bias[n];
            if (resid) c += resid[(size_t)r * N + n];
            if (relu) c = fmaxf(c, 0.0f);
            o[j] = c;
        }
        *(float4*)&C[(size_t)r * N + n0 + tx * 4] = make_float4(o[0], o[1], o[2], o[3]);
    }
}

// ---------------- split qkv into head-major Q/K/V; pre-scale Q ----------------
__global__ void split_heads_kernel(const float* __restrict__ qkv)
{
    int idx = blockIdx.x * 256 + threadIdx.x;   // over MT*192
    if (idx >= MT * 192) return;
    int m = idx / 192, c = idx % 192;
    float v = qkv[idx];
    int part = c >> 6, cc = c & 63;
    int h = cc >> 3, d = cc & 7;
    int o = h * (MT * HDD) + m * HDD + d;
    if (part == 0)      g_qh[o] = v * (QSCALE * LOG2E_F);
    else if (part == 1) g_kh[o] = v;
    else                g_vh[o] = v;
}

// ---------------- attention: grid (M/64, NH), block 128 (4 warps split keys) -------------
// per warp: all 64 queries (2/thread), 1/4 of keys; unnormalized exp-sums combined in smem.
__global__ void attn_kernel()
{
    __shared__ float sm[8192];   // 32KB: per-warp K/V tiles, reused for reduction
    const int h = blockIdx.y;
    const int q0 = blockIdx.x * 64;
    const int tid = threadIdx.x;
    const int w = tid >> 5, lane = tid & 31;
    const float* Qb = g_qh + h * MT * HDD;
    const float* Kb = g_kh + h * MT * HDD;
    const float* Vb = g_vh + h * MT * HDD;

    ull q[2][4], o[2][4];
    float l[2];
#pragma unroll
    for (int i = 0; i < 2; i++) {
        int qm = q0 + lane + 32 * i;
        const ull* qr = (const ull*)(Qb + qm * 8);
#pragma unroll
        for (int j = 0; j < 4; j++) { q[i][j] = qr[j]; o[i][j] = 0ULL; }
        l[i] = 0.0f;
    }

    float* ksw = sm + w * 2048;
    float* vsw = ksw + 1024;

    for (int kt = w; kt < 32; kt += 4) {        // 128-key tiles
        __syncwarp();
        const float4* Ksrc = (const float4*)(Kb + kt * 1024);
        const float4* Vsrc = (const float4*)(Vb + kt * 1024);
        for (int u = lane; u < 256; u += 32) {
            ((float4*)ksw)[u] = Ksrc[u];
            ((float4*)vsw)[u] = Vsrc[u];
        }
        __syncwarp();
        const ull* kq = (const ull*)ksw;
        const ull* vq = (const ull*)vsw;
#pragma unroll 2
        for (int j = 0; j < 128; j++) {
            ull k0 = kq[4*j], k1 = kq[4*j+1], k2 = kq[4*j+2], k3 = kq[4*j+3];
            ull v0 = vq[4*j], v1 = vq[4*j+1], v2 = vq[4*j+2], v3 = vq[4*j+3];
#pragma unroll
            for (int i = 0; i < 2; i++) {
                ull s2 = fma2(q[i][0], k0, fma2(q[i][1], k1, fma2(q[i][2], k2, fma2(q[i][3], k3, 0ULL))));
                float slo, shi; unpack2(s2, slo, shi);
                float p = ex2f(slo + shi);        // q pre-scaled by scale*log2e
                l[i] += p;
                ull pp = pack2(p, p);
                o[i][0] = fma2(pp, v0, o[i][0]);
                o[i][1] = fma2(pp, v1, o[i][1]);
                o[i][2] = fma2(pp, v2, o[i][2]);
                o[i][3] = fma2(pp, v3, o[i][3]);
            }
        }
    }

    __syncthreads();
    float* red  = sm;            // [4][64][8]
    float* lred = sm + 4*64*8;   // [4][64]
#pragma unroll
    for (int i = 0; i < 2; i++) {
        int ql = lane + 32 * i;
#pragma unroll
        for (int jj = 0; jj < 4; jj++) {
            float a, b; unpack2(o[i][jj], a, b);
            red[(w * 64 + ql) * 8 + 2 * jj]     = a;
            red[(w * 64 + ql) * 8 + 2 * jj + 1] = b;
        }
        lred[w * 64 + ql] = l[i];
    }
    __syncthreads();
    if (tid < 64) {
        int qm = q0 + tid;
        float ls = lred[tid] + lred[64 + tid] + lred[128 + tid] + lred[192 + tid];
        float inv = 1.0f / ls;
#pragma unroll
        for (int d = 0; d < 8; d++) {
            float s = red[tid * 8 + d] + red[(64 + tid) * 8 + d]
                    + red[(128 + tid) * 8 + d] + red[(192 + tid) * 8 + d];
            g_attn[qm * 64 + h * 8 + d] = s * inv;
        }
    }
}

// ---------------- layernorm: one thread per row ----------------
__global__ void ln_kernel(const float* __restrict__ X, const float* __restrict__ w,
                          const float* __restrict__ b, float* __restrict__ out)
{
    int m = blockIdx.x * 256 + threadIdx.x;
    const float4* xr = (const float4*)(X + (size_t)m * 64);
    float4 v[16];
    float s = 0.0f;
#pragma unroll
    for (int t = 0; t < 16; t++) { v[t] = xr[t]; s += v[t].x + v[t].y + v[t].z + v[t].w; }
    float mu = s * (1.0f / 64.0f);
    float var = 0.0f;
#pragma unroll
    for (int t = 0; t < 16; t++) {
        float a = v[t].x - mu, b2 = v[t].y - mu, c = v[t].z - mu, d = v[t].w - mu;
        var += a * a + b2 * b2 + c * c + d * d;
    }
    float inv = rsqrtf(var * (1.0f / 64.0f) + LNEPS);
    const float4* wr = (const float4*)w;
    const float4* br = (const float4*)b;
    float4* orow = (float4*)(out + (size_t)m * 64);
#pragma unroll
    for (int t = 0; t < 16; t++) {
        float4 ww = wr[t], bb = br[t], r;
        r.x = (v[t].x - mu) * inv * ww.x + bb.x;
        r.y = (v[t].y - mu) * inv * ww.y + bb.y;
        r.z = (v[t].z - mu) * inv * ww.z + bb.z;
        r.w = (v[t].w - mu) * inv * ww.w + bb.w;
        orow[t] = r;
    }
}

// ---------------- prune + write x output ----------------
__global__ void prune_kernel(const float* __restrict__ mask, float* __restrict__ dout)
{
    int idx = blockIdx.x * 256 + threadIdx.x;   // MT*DM
    float v = g_xbuf[idx] * mask[idx & 63];
    g_xp[idx] = v;
    dout[idx] = v;
}

// ---------------- half-norms (times log2e); also zero gram accumulators ---------------
__global__ void norms_kernel(const float* __restrict__ y)
{
    int idx = blockIdx.x * 256 + threadIdx.x;   // 2*MT
    if (idx == 0) { g_acc[0] = 0.f; g_acc[1] = 0.f; g_acc[2] = 0.f; }
    const float* src; float* dst; int m;
    if (idx < MT) { src = g_xp; dst = g_hnx; m = idx; }
    else          { src = y;    dst = g_hny; m = idx - MT; }
    const float4* r = (const float4*)(src + (size_t)m * 64);
    float s = 0.0f;
#pragma unroll
    for (int t = 0; t < 16; t++) {
        float4 v = r[t];
        s += v.x * v.x + v.y * v.y + v.z * v.z + v.w * v.w;
    }
    dst[m] = s * (0.5f * LOG2E_F);
}

// ---------------- gram sum: sum exp(a.b - hna - hnb), 64x64 tiles ----------------
__global__ void gram_kernel(const float* __restrict__ A, const float* __restrict__ B,
                            const float* __restrict__ hna, const float* __restrict__ hnb,
                            int KD, int sym, float* __restrict__ acc)
{
    int bi = blockIdx.x, bj = blockIdx.y;
    if (sym && bj < bi) return;
    __shared__ float As[64][68], Bs[64][68];
    __shared__ float rs[256];
    const int tid = threadIdx.x;
    const int tx = tid & 15, ty = tid >> 4;
    const int a0 = bi * 64, b0 = bj * 64;

    for (int t = tid; t < 1024; t += 256) {
        int rr = t >> 4, kq = (t & 15) << 2;
        *(float4*)&As[rr][kq] = *(const float4*)&A[(size_t)(a0 + rr) * 64 + kq];
        *(float4*)&Bs[rr][kq] = *(const float4*)&B[(size_t)(b0 + rr) * 64 + kq];
    }
    __syncthreads();

    ull acc2[4][4];
#pragma unroll
    for (int i = 0; i < 4; i++)
#pragma unroll
        for (int j = 0; j < 4; j++) acc2[i][j] = 0ULL;

    int KH = KD >> 1;
#pragma unroll 4
    for (int kk = 0; kk < KH; kk++) {
        ull a[4], b[4];
#pragma unroll
        for (int i = 0; i < 4; i++) a[i] = *(const ull*)&As[ty * 4 + i][kk * 2];
#pragma unroll
        for (int j = 0; j < 4; j++) b[j] = *(const ull*)&Bs[tx * 4 + j][kk * 2];
#pragma unroll
        for (int i = 0; i < 4; i++)
#pragma unroll
            for (int j = 0; j < 4; j++) acc2[i][j] = fma2(a[i], b[j], acc2[i][j]);
    }

    float ha[4], hb[4];
#pragma unroll
    for (int i = 0; i < 4; i++) ha[i] = hna[a0 + ty * 4 + i];
#pragma unroll
    for (int j = 0; j < 4; j++) hb[j] = hnb[b0 + tx * 4 + j];

    float s = 0.0f;
#pragma unroll
    for (int i = 0; i < 4; i++)
#pragma unroll
        for (int j = 0; j < 4; j++) {
            float lo, hi; unpack2(acc2[i][j], lo, hi);
            float dot = lo + hi;
            s += ex2f(__fmaf_rn(dot, LOG2E_F, -(ha[i] + hb[j])));
        }

    rs[tid] = s;
    __syncthreads();
    for (int st = 128; st > 0; st >>= 1) {
        if (tid < st) rs[tid] += rs[tid + st];
        __syncthreads();
    }
    if (tid == 0) {
        float w = (sym && bi != bj) ? 2.0f : 1.0f;
        atomicAdd(acc, rs[0] * w);
    }
}

__global__ void finalize_kernel(float* __restrict__ dout, int pos)
{
    dout[pos] = (g_acc[0] + g_acc[1] - 2.0f * g_acc[2]) * (1.0f / (4096.0f * 4096.0f));
}

// ---------------- host side ----------------
extern "C" void kernel_launch(void* const* d_in, const int* in_sizes, int n_in,
                              void* d_out, int out_size)
{
    const float* hsi  = (const float*)d_in[0];
    const float* rgb  = (const float*)d_in[1];
    const float* in_w = (const float*)d_in[2];
    const float* in_b = (const float*)d_in[3];
    const float* ow   = (const float*)d_in[4];
    const float* ob   = (const float*)d_in[5];
    const float* l1w  = (const float*)d_in[6];
    const float* l1b  = (const float*)d_in[7];
    const float* l2w  = (const float*)d_in[8];
    const float* l2b  = (const float*)d_in[9];
    const float* n1w  = (const float*)d_in[10];
    const float* n1b  = (const float*)d_in[11];
    const float* n2w  = (const float*)d_in[12];
    const float* n2b  = (const float*)d_in[13];
    const float* mask = (const float*)d_in[14];
    float* out = (float*)d_out;

    float *xbuf, *x1, *tmp, *big, *attn, *xp, *hnx, *hny, *acc;
    cudaGetSymbolAddress((void**)&xbuf, g_xbuf);
    cudaGetSymbolAddress((void**)&x1,   g_x1);
    cudaGetSymbolAddress((void**)&tmp,  g_tmp);
    cudaGetSymbolAddress((void**)&big,  g_big);
    cudaGetSymbolAddress((void**)&attn, g_attn);
    cudaGetSymbolAddress((void**)&xp,   g_xp);
    cudaGetSymbolAddress((void**)&hnx,  g_hnx);
    cudaGetSymbolAddress((void**)&hny,  g_hny);
    cudaGetSymbolAddress((void**)&acc,  g_acc);

    for (int i = 0; i < NLAYER; i++) {
        const float* xin = (i == 0) ? hsi : xbuf;
        gemm_kernel<<<dim3(64, 3), 256>>>(xin, in_w + i * 192 * 64, in_b + i * 192,
                                          nullptr, big, 192, 64, 0);
        split_heads_kernel<<<3072, 256>>>(big);
        attn_kernel<<<dim3(64, 8), 128>>>();
        gemm_kernel<<<dim3(64, 1), 256>>>(attn, ow + i * 64 * 64, ob + i * 64,
                                          xin, tmp, 64, 64, 0);
        ln_kernel<<<16, 256>>>(tmp, n1w + i * 64, n1b + i * 64, x1);
        gemm_kernel<<<dim3(64, 4), 256>>>(x1, l1w + i * 256 * 64, l1b + i * 256,
                                          nullptr, big, 256, 64, 1);
        gemm_kernel<<<dim3(64, 1), 256>>>(big, l2w + i * 64 * 256, l2b + i * 64,
                                          x1, tmp, 64, 256, 0);
        ln_kernel<<<16, 256>>>(tmp, n2w + i * 64, n2b + i * 64, xbuf);
    }

    prune_kernel<<<1024, 256>>>(mask, out);
    norms_kernel<<<32, 256>>>(rgb);
    gram_kernel<<<dim3(64, 64), 256>>>(xp,  xp,  hnx, hnx, 20, 1, acc + 0);
    gram_kernel<<<dim3(64, 64), 256>>>(rgb, rgb, hny, hny, 64, 1, acc + 1);
    gram_kernel<<<dim3(64, 64), 256>>>(xp,  rgb, hnx, hny, 20, 0, acc + 2);
    finalize_kernel<<<1, 1>>>(out, out_size - 1);
}

// round 2
// speedup vs baseline: 1.1493x; 1.1493x over previous
#include <cuda_runtime.h>

typedef unsigned long long ull;

#define MT 4096        // tokens
#define DM 64          // d_model
#define NHH 8          // heads
#define HDD 8          // head dim
#define NLAYER 4
#define DFFN 256
#define LNEPS 1e-5f
#define LOG2E_F 1.4426950408889634f
#define QSCALE 0.35355339059327373f   // 1/sqrt(8)

// ---------------- scratch (device globals; no runtime alloc) ----------------
__device__ float g_xbuf[MT*DM];
__device__ float g_x1[MT*DM];
__device__ float g_big[MT*DFFN];     // ff hidden (256)
__device__ float g_qh[MT*DM];        // [NH][M][HD], q pre-scaled by QSCALE*LOG2E
__device__ float g_kh[MT*DM];
__device__ float g_vh[MT*DM];
__device__ float g_attn[MT*DM];
__device__ float g_xp[MT*DM];        // pruned x
__device__ float g_hnx[MT];          // 0.5*|x|^2*log2e
__device__ float g_hny[MT];
__device__ float g_acc[3];           // gram sums: xx, yy, xy

// ---------------- f32x2 helpers ----------------
__device__ __forceinline__ ull fma2(ull a, ull b, ull c) {
    ull d; asm("fma.rn.f32x2 %0, %1, %2, %3;" : "=l"(d) : "l"(a), "l"(b), "l"(c)); return d;
}
__device__ __forceinline__ ull pack2(float a, float b) {
    ull r; asm("mov.b64 %0, {%1, %2};" : "=l"(r) : "f"(a), "f"(b)); return r;
}
__device__ __forceinline__ void unpack2(ull v, float& a, float& b) {
    asm("mov.b64 {%0, %1}, %2;" : "=f"(a), "=f"(b) : "l"(v));
}
__device__ __forceinline__ float ex2f(float x) {
    float r; asm("ex2.approx.f32 %0, %1;" : "=f"(r) : "f"(x)); return r;
}

// ================= QKV GEMM: [M,64] @ [192,64]^T, epilogue splits heads ==========
// grid (64, 3), block 256. blockIdx.y = part (0=Q,1=K,2=V).
__global__ void qkv_gemm_kernel(const float* __restrict__ A, const float* __restrict__ W,
                                const float* __restrict__ bias)
{
    __shared__ float As[64][68];
    __shared__ float Ws[64][68];
    const int tid = threadIdx.x;
    const int r0 = blockIdx.x * 64;
    const int part = blockIdx.y;
    const int n0 = part * 64;
    const int tx = tid & 15, ty = tid >> 4;

    for (int t = tid; t < 1024; t += 256) {
        int rr = t >> 4, kq = (t & 15) << 2;
        *(float4*)&As[rr][kq] = *(const float4*)&A[(size_t)(r0 + rr) * 64 + kq];
        *(float4*)&Ws[rr][kq] = *(const float4*)&W[(size_t)(n0 + rr) * 64 + kq];
    }
    __syncthreads();

    ull acc[4][4];
#pragma unroll
    for (int i = 0; i < 4; i++)
#pragma unroll
        for (int j = 0; j < 4; j++) acc[i][j] = 0ULL;

#pragma unroll 8
    for (int kk = 0; kk < 32; kk++) {
        ull a[4], w[4];
#pragma unroll
        for (int i = 0; i < 4; i++) a[i] = *(const ull*)&As[ty * 4 + i][kk * 2];
#pragma unroll
        for (int j = 0; j < 4; j++) w[j] = *(const ull*)&Ws[tx * 4 + j][kk * 2];
#pragma unroll
        for (int i = 0; i < 4; i++)
#pragma unroll
            for (int j = 0; j < 4; j++) acc[i][j] = fma2(a[i], w[j], acc[i][j]);
    }

    float* dst = (part == 0) ? g_qh : (part == 1) ? g_kh : g_vh;
    const float qs = (part == 0) ? (QSCALE * LOG2E_F) : 1.0f;
    const int cc = tx * 4;              // 0..63 within part; 4-aligned => same head
    const int h = cc >> 3, d0 = cc & 7;
#pragma unroll
    for (int i = 0; i < 4; i++) {
        int r = r0 + ty * 4 + i;
        float o[4];
#pragma unroll
        for (int j = 0; j < 4; j++) {
            float lo, hi; unpack2(acc[i][j], lo, hi);
            o[j] = (lo + hi + bias[n0 + cc + j]) * qs;
        }
        *(float4*)&dst[(size_t)h * MT * HDD + (size_t)r * HDD + d0] =
            make_float4(o[0], o[1], o[2], o[3]);
    }
}

// ================= FF1 GEMM: [M,64] @ [256,64]^T + bias + relu -> g_big ==========
// grid (64, 4), block 256.
__global__ void ff1_gemm_kernel(const float* __restrict__ A, const float* __restrict__ W,
                                const float* __restrict__ bias)
{
    __shared__ float As[64][68];
    __shared__ float Ws[64][68];
    const int tid = threadIdx.x;
    const int r0 = blockIdx.x * 64, n0 = blockIdx.y * 64;
    const int tx = tid & 15, ty = tid >> 4;

    for (int t = tid; t < 1024; t += 256) {
        int rr = t >> 4, kq = (t & 15) << 2;
        *(float4*)&As[rr][kq] = *(const float4*)&A[(size_t)(r0 + rr) * 64 + kq];
        *(float4*)&Ws[rr][kq] = *(const float4*)&W[(size_t)(n0 + rr) * 64 + kq];
    }
    __syncthreads();

    ull acc[4][4];
#pragma unroll
    for (int i = 0; i < 4; i++)
#pragma unroll
        for (int j = 0; j < 4; j++) acc[i][j] = 0ULL;

#pragma unroll 8
    for (int kk = 0; kk < 32; kk++) {
        ull a[4], w[4];
#pragma unroll
        for (int i = 0; i < 4; i++) a[i] = *(const ull*)&As[ty * 4 + i][kk * 2];
#pragma unroll
        for (int j = 0; j < 4; j++) w[j] = *(const ull*)&Ws[tx * 4 + j][kk * 2];
#pragma unroll
        for (int i = 0; i < 4; i++)
#pragma unroll
            for (int j = 0; j < 4; j++) acc[i][j] = fma2(a[i], w[j], acc[i][j]);
    }

#pragma unroll
    for (int i = 0; i < 4; i++) {
        int r = r0 + ty * 4 + i;
        float o[4];
#pragma unroll
        for (int j = 0; j < 4; j++) {
            float lo, hi; unpack2(acc[i][j], lo, hi);
            o[j] = fmaxf(lo + hi + bias[n0 + tx * 4 + j], 0.0f);
        }
        *(float4*)&g_big[(size_t)r * DFFN + n0 + tx * 4] = make_float4(o[0], o[1], o[2], o[3]);
    }
}

// ===== GEMM (N=64) + residual + LayerNorm (+ optional prune/out/halfnorm) =======
// C0[M,64] = A[M,K] @ W[64,K]^T; v = C0 + bias + resid; out = LN(v)*lnw+lnb
// if mask: out *= mask, also write out2 (d_out) and hn (0.5*|row|^2*log2e).
// grid 128 (32-row tiles), block 256. Thread: 2 rows x 4 cols.
__global__ void gemm_ln_kernel(const float* __restrict__ A, const float* __restrict__ W,
                               const float* __restrict__ bias, const float* __restrict__ resid,
                               const float* __restrict__ lnw, const float* __restrict__ lnb,
                               float* __restrict__ out, int K,
                               const float* __restrict__ mask, float* __restrict__ out2,
                               float* __restrict__ hn)
{
    __shared__ float As[32][68];
    __shared__ float Ws[64][68];
    const int tid = threadIdx.x;
    const int r0 = blockIdx.x * 32;
    const int tx = tid & 15, ty = tid >> 4;

    ull acc[2][4];
#pragma unroll
    for (int i = 0; i < 2; i++)
#pragma unroll
        for (int j = 0; j < 4; j++) acc[i][j] = 0ULL;

    for (int kc = 0; kc < K; kc += 64) {
        __syncthreads();
        for (int t = tid; t < 512; t += 256) {
            int rr = t >> 4, kq = (t & 15) << 2;
            *(float4*)&As[rr][kq] = *(const float4*)&A[(size_t)(r0 + rr) * K + kc + kq];
        }
        for (int t = tid; t < 1024; t += 256) {
            int rr = t >> 4, kq = (t & 15) << 2;
            *(float4*)&Ws[rr][kq] = *(const float4*)&W[(size_t)rr * K + kc + kq];
        }
        __syncthreads();
#pragma unroll 8
        for (int kk = 0; kk < 32; kk++) {
            ull a0 = *(const ull*)&As[ty * 2][kk * 2];
            ull a1 = *(const ull*)&As[ty * 2 + 1][kk * 2];
            ull w[4];
#pragma unroll
            for (int j = 0; j < 4; j++) w[j] = *(const ull*)&Ws[tx * 4 + j][kk * 2];
#pragma unroll
            for (int j = 0; j < 4; j++) {
                acc[0][j] = fma2(a0, w[j], acc[0][j]);
                acc[1][j] = fma2(a1, w[j], acc[1][j]);
            }
        }
    }

#pragma unroll
    for (int i = 0; i < 2; i++) {
        int r = r0 + ty * 2 + i;
        float v[4];
#pragma unroll
        for (int j = 0; j < 4; j++) {
            int n = tx * 4 + j;
            float lo, hi; unpack2(acc[i][j], lo, hi);
            v[j] = lo + hi + bias[n] + resid[(size_t)r * 64 + n];
        }
        float s = v[0] + v[1] + v[2] + v[3];
#pragma unroll
        for (int ml = 8; ml; ml >>= 1) s += __shfl_xor_sync(0xffffffffu, s, ml, 16);
        float mu = s * (1.0f / 64.0f);
        float q = 0.0f;
#pragma unroll
        for (int j = 0; j < 4; j++) { float d = v[j] - mu; q += d * d; }
#pragma unroll
        for (int ml = 8; ml; ml >>= 1) q += __shfl_xor_sync(0xffffffffu, q, ml, 16);
        float inv = rsqrtf(q * (1.0f / 64.0f) + LNEPS);
        float o[4], ss = 0.0f;
#pragma unroll
        for (int j = 0; j < 4; j++) {
            int n = tx * 4 + j;
            float t = (v[j] - mu) * inv * lnw[n] + lnb[n];
            if (mask) { t *= mask[n]; ss += t * t; }
            o[j] = t;
        }
        float4 o4 = make_float4(o[0], o[1], o[2], o[3]);
        *(float4*)&out[(size_t)r * 64 + tx * 4] = o4;
        if (mask) {
            *(float4*)&out2[(size_t)r * 64 + tx * 4] = o4;
#pragma unroll
            for (int ml = 8; ml; ml >>= 1) ss += __shfl_xor_sync(0xffffffffu, ss, ml, 16);
            if (tx == 0) hn[r] = ss * (0.5f * LOG2E_F);
        }
    }
}

// ---------------- attention: grid (64, 8), block 256 (8 warps split keys) ----------
__global__ void attn_kernel()
{
    __shared__ float sm[8192];   // 32KB: per-warp 64-key K/V tiles; reused for reduction
    const int h = blockIdx.y;
    const int q0 = blockIdx.x * 64;
    const int tid = threadIdx.x;
    const int w = tid >> 5, lane = tid & 31;
    const float* Qb = g_qh + (size_t)h * MT * HDD;
    const float* Kb = g_kh + (size_t)h * MT * HDD;
    const float* Vb = g_vh + (size_t)h * MT * HDD;

    ull q[2][4], o[2][4];
    float l[2];
#pragma unroll
    for (int i = 0; i < 2; i++) {
        int qm = q0 + lane + 32 * i;
        const ull* qr = (const ull*)(Qb + (size_t)qm * 8);
#pragma unroll
        for (int j = 0; j < 4; j++) { q[i][j] = qr[j]; o[i][j] = 0ULL; }
        l[i] = 0.0f;
    }

    float* ksw = sm + w * 1024;
    float* vsw = ksw + 512;

    for (int kt = w; kt < 64; kt += 8) {        // 64-key tiles, keys split across 8 warps
        __syncwarp();
        const float4* Ks = (const float4*)(Kb + (size_t)kt * 512);
        const float4* Vs = (const float4*)(Vb + (size_t)kt * 512);
#pragma unroll
        for (int u = lane; u < 128; u += 32) {
            ((float4*)ksw)[u] = Ks[u];
            ((float4*)vsw)[u] = Vs[u];
        }
        __syncwarp();
        const ull* kq = (const ull*)ksw;
        const ull* vq = (const ull*)vsw;
#pragma unroll 4
        for (int j = 0; j < 64; j++) {
            ull k0 = kq[4*j], k1 = kq[4*j+1], k2 = kq[4*j+2], k3 = kq[4*j+3];
            ull v0 = vq[4*j], v1 = vq[4*j+1], v2 = vq[4*j+2], v3 = vq[4*j+3];
#pragma unroll
            for (int i = 0; i < 2; i++) {
                ull s0 = fma2(q[i][0], k0, fma2(q[i][2], k2, 0ULL));
                ull s1 = fma2(q[i][1], k1, fma2(q[i][3], k3, 0ULL));
                float a0, b0, a1, b1;
                unpack2(s0, a0, b0); unpack2(s1, a1, b1);
                float p = ex2f((a0 + a1) + (b0 + b1));   // q pre-scaled by scale*log2e
                l[i] += p;
                ull pp = pack2(p, p);
                o[i][0] = fma2(pp, v0, o[i][0]);
                o[i][1] = fma2(pp, v1, o[i][1]);
                o[i][2] = fma2(pp, v2, o[i][2]);
                o[i][3] = fma2(pp, v3, o[i][3]);
            }
        }
    }

    __syncthreads();
    float* red  = sm;              // [8][64][8]
    float* lred = sm + 8*64*8;     // [8][64]
#pragma unroll
    for (int i = 0; i < 2; i++) {
        int ql = lane + 32 * i;
#pragma unroll
        for (int jj = 0; jj < 4; jj++) {
            float a, b; unpack2(o[i][jj], a, b);
            red[(w * 64 + ql) * 8 + 2 * jj]     = a;
            red[(w * 64 + ql) * 8 + 2 * jj + 1] = b;
        }
        lred[w * 64 + ql] = l[i];
    }
    __syncthreads();
    if (tid < 64) {
        int qm = q0 + tid;
        float ls = 0.0f;
#pragma unroll
        for (int ww = 0; ww < 8; ww++) ls += lred[ww * 64 + tid];
        float inv = 1.0f / ls;
#pragma unroll
        for (int d = 0; d < 8; d++) {
            float s = 0.0f;
#pragma unroll
            for (int ww = 0; ww < 8; ww++) s += red[(ww * 64 + tid) * 8 + d];
            g_attn[(size_t)qm * 64 + h * 8 + d] = s * inv;
        }
    }
}

// ---------------- half-norms for rgb; also zero gram accumulators ---------------
__global__ void normsy_kernel(const float* __restrict__ y)
{
    int m = blockIdx.x * 256 + threadIdx.x;   // MT
    if (m == 0) { g_acc[0] = 0.f; g_acc[1] = 0.f; g_acc[2] = 0.f; }
    const float4* r = (const float4*)(y + (size_t)m * 64);
    float s = 0.0f;
#pragma unroll
    for (int t = 0; t < 16; t++) {
        float4 v = r[t];
        s += v.x * v.x + v.y * v.y + v.z * v.z + v.w * v.w;
    }
    g_hny[m] = s * (0.5f * LOG2E_F);
}

// ---------------- gram sum: sum exp(a.b - hna - hnb), 64x64 tiles ----------------
__global__ void gram_kernel(const float* __restrict__ A, const float* __restrict__ B,
                            const float* __restrict__ hna, const float* __restrict__ hnb,
                            int KD, int sym, float* __restrict__ acc)
{
    int bi = blockIdx.x, bj = blockIdx.y;
    if (sym && bj < bi) return;
    __shared__ float As[64][68], Bs[64][68];
    __shared__ float rs[256];
    const int tid = threadIdx.x;
    const int tx = tid & 15, ty = tid >> 4;
    const int a0 = bi * 64, b0 = bj * 64;

    for (int t = tid; t < 1024; t += 256) {
        int rr = t >> 4, kq = (t & 15) << 2;
        *(float4*)&As[rr][kq] = *(const float4*)&A[(size_t)(a0 + rr) * 64 + kq];
        *(float4*)&Bs[rr][kq] = *(const float4*)&B[(size_t)(b0 + rr) * 64 + kq];
    }
    __syncthreads();

    ull acc2[4][4];
#pragma unroll
    for (int i = 0; i < 4; i++)
#pragma unroll
        for (int j = 0; j < 4; j++) acc2[i][j] = 0ULL;

    int KH = KD >> 1;
#pragma unroll 4
    for (int kk = 0; kk < KH; kk++) {
        ull a[4], b[4];
#pragma unroll
        for (int i = 0; i < 4; i++) a[i] = *(const ull*)&As[ty * 4 + i][kk * 2];
#pragma unroll
        for (int j = 0; j < 4; j++) b[j] = *(const ull*)&Bs[tx * 4 + j][kk * 2];
#pragma unroll
        for (int i = 0; i < 4; i++)
#pragma unroll
            for (int j = 0; j < 4; j++) acc2[i][j] = fma2(a[i], b[j], acc2[i][j]);
    }

    float ha[4], hb[4];
#pragma unroll
    for (int i = 0; i < 4; i++) ha[i] = hna[a0 + ty * 4 + i];
#pragma unroll
    for (int j = 0; j < 4; j++) hb[j] = hnb[b0 + tx * 4 + j];

    float s = 0.0f;
#pragma unroll
    for (int i = 0; i < 4; i++)
#pragma unroll
        for (int j = 0; j < 4; j++) {
            float lo, hi; unpack2(acc2[i][j], lo, hi);
            float dot = lo + hi;
            s += ex2f(__fmaf_rn(dot, LOG2E_F, -(ha[i] + hb[j])));
        }

    rs[tid] = s;
    __syncthreads();
    for (int st = 128; st > 0; st >>= 1) {
        if (tid < st) rs[tid] += rs[tid + st];
        __syncthreads();
    }
    if (tid == 0) {
        float w = (sym && bi != bj) ? 2.0f : 1.0f;
        atomicAdd(acc, rs[0] * w);
    }
}

__global__ void finalize_kernel(float* __restrict__ dout, int pos)
{
    dout[pos] = (g_acc[0] + g_acc[1] - 2.0f * g_acc[2]) * (1.0f / (4096.0f * 4096.0f));
}

// ---------------- host side ----------------
extern "C" void kernel_launch(void* const* d_in, const int* in_sizes, int n_in,
                              void* d_out, int out_size)
{
    const float* hsi  = (const float*)d_in[0];
    const float* rgb  = (const float*)d_in[1];
    const float* in_w = (const float*)d_in[2];
    const float* in_b = (const float*)d_in[3];
    const float* ow   = (const float*)d_in[4];
    const float* ob   = (const float*)d_in[5];
    const float* l1w  = (const float*)d_in[6];
    const float* l1b  = (const float*)d_in[7];
    const float* l2w  = (const float*)d_in[8];
    const float* l2b  = (const float*)d_in[9];
    const float* n1w  = (const float*)d_in[10];
    const float* n1b  = (const float*)d_in[11];
    const float* n2w  = (const float*)d_in[12];
    const float* n2b  = (const float*)d_in[13];
    const float* mask = (const float*)d_in[14];
    float* out = (float*)d_out;

    float *xbuf, *x1, *big, *attn, *xp, *hnx, *hny, *acc;
    cudaGetSymbolAddress((void**)&xbuf, g_xbuf);
    cudaGetSymbolAddress((void**)&x1,   g_x1);
    cudaGetSymbolAddress((void**)&big,  g_big);
    cudaGetSymbolAddress((void**)&attn, g_attn);
    cudaGetSymbolAddress((void**)&xp,   g_xp);
    cudaGetSymbolAddress((void**)&hnx,  g_hnx);
    cudaGetSymbolAddress((void**)&hny,  g_hny);
    cudaGetSymbolAddress((void**)&acc,  g_acc);

    for (int i = 0; i < NLAYER; i++) {
        const float* xin = (i == 0) ? hsi : xbuf;
        int last = (i == NLAYER - 1);
        qkv_gemm_kernel<<<dim3(64, 3), 256>>>(xin, in_w + i * 12288, in_b + i * 192);
        attn_kernel<<<dim3(64, 8), 256>>>();
        gemm_ln_kernel<<<128, 256>>>(attn, ow + i * 4096, ob + i * 64, xin,
                                     n1w + i * 64, n1b + i * 64, x1, 64,
                                     nullptr, nullptr, nullptr);
        ff1_gemm_kernel<<<dim3(64, 4), 256>>>(x1, l1w + i * 16384, l1b + i * 256);
        gemm_ln_kernel<<<128, 256>>>(big, l2w + i * 16384, l2b + i * 64, x1,
                                     n2w + i * 64, n2b + i * 64,
                                     last ? xp : xbuf, 256,
                                     last ? mask : nullptr,
                                     last ? out : nullptr,
                                     last ? hnx : nullptr);
    }

    normsy_kernel<<<16, 256>>>(rgb);
    gram_kernel<<<dim3(64, 64), 256>>>(xp,  xp,  hnx, hnx, 20, 1, acc + 0);
    gram_kernel<<<dim3(64, 64), 256>>>(rgb, rgb, hny, hny, 64, 1, acc + 1);
    gram_kernel<<<dim3(64, 64), 256>>>(xp,  rgb, hnx, hny, 20, 0, acc + 2);
    finalize_kernel<<<1, 1>>>(out, out_size - 1);
}